// round 11
// baseline (speedup 1.0000x reference)
#include <cuda_runtime.h>
#include <cstdint>

typedef unsigned long long ull;

// Problem constants
#define BB 128
#define SS 1024
#define FF 512
#define HH 32
#define GG 128              // 4*H
#define NTOK (BB*SS)        // 131072

// Scratch (device globals: allocation-free, graph-capturable)
__device__ __align__(16) float g_xg[(size_t)NTOK * GG];  // PERMUTED: [tok][4*j+gate]
__device__ __align__(16) float g_hs[(size_t)NTOK * HH];
__device__ __align__(16) float g_wxp[64 * GG];           // permuted Wx
__device__ __align__(16) float g_blp[GG];                // permuted bl

// ---------------------------------------------------------------------------
// helpers
// ---------------------------------------------------------------------------
__device__ __forceinline__ ull pk2(float lo, float hi) {
    ull r; asm("mov.b64 %0, {%1,%2};" : "=l"(r) : "f"(lo), "f"(hi)); return r;
}
__device__ __forceinline__ void upk2(ull v, float& lo, float& hi) {
    asm("mov.b64 {%0,%1}, %2;" : "=f"(lo), "=f"(hi) : "l"(v));
}
__device__ __forceinline__ void fma2(ull& d, ull a, ull b) {
    asm("fma.rn.f32x2 %0, %1, %2, %0;" : "+l"(d) : "l"(a), "l"(b));
}
__device__ __forceinline__ ull add2(ull a, ull b) {
    ull r; asm("add.rn.f32x2 %0, %1, %2;" : "=l"(r) : "l"(a), "l"(b)); return r;
}

// MUFU-based activations — used ONLY in the LSTM recurrence
__device__ __forceinline__ float sigf(float x) {
    return __fdividef(1.f, 1.f + __expf(-x));
}
__device__ __forceinline__ float tanhfast(float x) {
    return 2.f * __fdividef(1.f, 1.f + __expf(-2.f * x)) - 1.f;
}

// MUFU-free reciprocal: integer seed + 3 Newton steps
__device__ __forceinline__ float rcp_nr(float q) {
    float r = __uint_as_float(0x7EF311C3u - __float_as_uint(q));
    r = r * (2.0f - q * r);
    r = r * (2.0f - q * r);
    r = r * (2.0f - q * r);
    return r;
}
// MUFU-free tanh: rational poly, |err| ~1e-6, pure fma/alu pipe
__device__ __forceinline__ float tanh_poly(float x) {
    const float cl = 7.90531110763549805f;
    x = fminf(cl, fmaxf(-cl, x));
    float x2 = x * x;
    float p = fmaf(x2, -2.76076847742355e-16f, 2.00018790482477e-13f);
    p = fmaf(x2, p, -8.60467152213735e-11f);
    p = fmaf(x2, p,  5.12229709037114e-08f);
    p = fmaf(x2, p,  1.48572235717979e-05f);
    p = fmaf(x2, p,  6.37261928875436e-04f);
    p = fmaf(x2, p,  4.89352455891786e-03f);
    p = p * x;
    float q = fmaf(x2, 1.19825839466702e-06f, 1.18534705686654e-04f);
    q = fmaf(x2, q, 2.26843463243900e-03f);
    q = fmaf(x2, q, 4.89352518554385e-03f);
    return p * rcp_nr(q);
}

// ---------------------------------------------------------------------------
// K0: permute Wx[64,128] and bl[128]: wxp[k][4j+g] = Wx[k][32g+j]
// ---------------------------------------------------------------------------
__global__ void k_perm(const float* __restrict__ Wx, const float* __restrict__ bl)
{
    int t = threadIdx.x;          // 0..127  (= 4j+g)
    int j = t >> 2, g = t & 3;
    int kb = blockIdx.x;
    if (kb < 64) g_wxp[kb * GG + t] = Wx[kb * GG + 32 * g + j];
    else         g_blp[t] = bl[32 * g + j];
}

// ---------------------------------------------------------------------------
// K1: front MLP (R8 version — measured good).
// ---------------------------------------------------------------------------
__global__ __launch_bounds__(256) void k_front(
    const float* __restrict__ x,  const float* __restrict__ W1, const float* __restrict__ b1,
    const float* __restrict__ W2, const float* __restrict__ b2)
{
    __shared__ float xs [64 * 68];
    __shared__ float h1s[64 * 36];
    __shared__ float h2s[64 * 68];

    const int tid  = threadIdx.x;
    const int tok0 = blockIdx.x * 64;

    // ---- GEMM1: [64,512] @ [512,32] ----
    const int c  = tid & 31;
    const int r8 = tid >> 5;
    float acc[8];
#pragma unroll
    for (int i = 0; i < 8; i++) acc[i] = 0.f;

    for (int kk = 0; kk < FF; kk += 64) {
        __syncthreads();
#pragma unroll
        for (int q = 0; q < 4; q++) {
            int idx  = tid + 256 * q;
            int trow = idx >> 4;
            int kq   = idx & 15;
            float4 v = *(const float4*)(x + (size_t)(tok0 + trow) * FF + kk + kq * 4);
            *(float4*)(xs + trow * 68 + kq * 4) = v;
        }
        __syncthreads();
#pragma unroll 4
        for (int k = 0; k < 64; k += 4) {
            float w0 = __ldg(W1 + (kk + k + 0) * 32 + c);
            float w1 = __ldg(W1 + (kk + k + 1) * 32 + c);
            float w2 = __ldg(W1 + (kk + k + 2) * 32 + c);
            float w3 = __ldg(W1 + (kk + k + 3) * 32 + c);
#pragma unroll
            for (int i = 0; i < 8; i++) {
                float4 xv = *(const float4*)(xs + (r8 * 8 + i) * 68 + k);
                acc[i] = fmaf(xv.w, w3, fmaf(xv.z, w2, fmaf(xv.y, w1, fmaf(xv.x, w0, acc[i]))));
            }
        }
    }
    {
        float bb = __ldg(b1 + c);
#pragma unroll
        for (int i = 0; i < 8; i++)
            h1s[(r8 * 8 + i) * 36 + c] = tanh_poly(acc[i] + bb);
    }
    __syncthreads();

    // ---- GEMM2: [64,32] @ [32,64] ----
    {
        const int c2 = tid & 63;
        const int rg = tid >> 6;
        float a2[16];
#pragma unroll
        for (int i = 0; i < 16; i++) a2[i] = 0.f;
#pragma unroll
        for (int k = 0; k < 32; k += 4) {
            float w0 = __ldg(W2 + (k + 0) * 64 + c2);
            float w1 = __ldg(W2 + (k + 1) * 64 + c2);
            float w2 = __ldg(W2 + (k + 2) * 64 + c2);
            float w3 = __ldg(W2 + (k + 3) * 64 + c2);
#pragma unroll
            for (int i = 0; i < 16; i++) {
                float4 xv = *(const float4*)(h1s + (rg * 16 + i) * 36 + k);
                a2[i] = fmaf(xv.w, w3, fmaf(xv.z, w2, fmaf(xv.y, w1, fmaf(xv.x, w0, a2[i]))));
            }
        }
        float bb = __ldg(b2 + c2);
#pragma unroll
        for (int i = 0; i < 16; i++)
            h2s[(rg * 16 + i) * 68 + c2] = tanh_poly(a2[i] + bb);
    }
    __syncthreads();

    // ---- GEMM3: [64,64] @ wxp[64,128] + blp -> g_xg (permuted layout) ----
    {
        const int c3 = tid & 127;
        const int rg = tid >> 7;
        float a3[32];
#pragma unroll
        for (int i = 0; i < 32; i++) a3[i] = 0.f;
#pragma unroll 4
        for (int k = 0; k < 64; k += 4) {
            float w0 = g_wxp[(k + 0) * GG + c3];
            float w1 = g_wxp[(k + 1) * GG + c3];
            float w2 = g_wxp[(k + 2) * GG + c3];
            float w3 = g_wxp[(k + 3) * GG + c3];
#pragma unroll
            for (int i = 0; i < 32; i++) {
                float4 xv = *(const float4*)(h2s + (rg * 32 + i) * 68 + k);
                a3[i] = fmaf(xv.w, w3, fmaf(xv.z, w2, fmaf(xv.y, w1, fmaf(xv.x, w0, a3[i]))));
            }
        }
        float bb = g_blp[c3];
#pragma unroll
        for (int i = 0; i < 32; i++)
            g_xg[(size_t)(tok0 + rg * 32 + i) * GG + c3] = a3[i] + bb;
    }
}

// ---------------------------------------------------------------------------
// K2: LSTM scan — TWO interleaved chains per warp (batches 2b, 2b+1).
// grid = 64, block = 32. Thread j = hidden unit j for both chains.
// Wh registers shared between chains; independent chains hide each other's
// latency (shfl + fma2 chain + MUFU chain). Prefetch ring depth 4 per chain.
// ---------------------------------------------------------------------------
__global__ __launch_bounds__(32, 1) void k_lstm(const float* __restrict__ Wh)
{
    const int b0 = blockIdx.x * 2;
    const int j  = threadIdx.x;

    ull wif[HH], wgo[HH];
#pragma unroll
    for (int k = 0; k < HH; k++) {
        const float* row = Wh + k * GG;
        wif[k] = pk2(__ldg(row + j),      __ldg(row + 32 + j));
        wgo[k] = pk2(__ldg(row + 64 + j), __ldg(row + 96 + j));
    }

    const float4* xgA = reinterpret_cast<const float4*>(g_xg) + (size_t)b0 * SS * 32 + j;
    const float4* xgB = xgA + (size_t)SS * 32;
    float* hsA = g_hs + (size_t)b0 * SS * HH + j;
    float* hsB = hsA + (size_t)SS * HH;

    float cA = 0.f, hA = 0.f, cB = 0.f, hB = 0.f;
    float4 pfA[4], pfB[4];
#pragma unroll
    for (int q = 0; q < 4; q++) {
        pfA[q] = __ldg(xgA + (size_t)q * 32);
        pfB[q] = __ldg(xgB + (size_t)q * 32);
    }

#pragma unroll 2
    for (int t = 0; t < SS; t++) {
        float4 gA = pfA[t & 3];
        float4 gB = pfB[t & 3];
        int tn = (t + 4 < SS) ? (t + 4) : (SS - 1);
        pfA[t & 3] = __ldg(xgA + (size_t)tn * 32);
        pfB[t & 3] = __ldg(xgB + (size_t)tn * 32);

        ull aifA0 = pk2(gA.x, gA.y), agoA0 = pk2(gA.z, gA.w);
        ull aifB0 = pk2(gB.x, gB.y), agoB0 = pk2(gB.z, gB.w);
        ull aifA1 = 0ull, agoA1 = 0ull, aifB1 = 0ull, agoB1 = 0ull;

#pragma unroll
        for (int k = 0; k < HH; k += 2) {
            float a0 = __shfl_sync(0xffffffffu, hA, k);
            float a1 = __shfl_sync(0xffffffffu, hA, k + 1);
            float b0v = __shfl_sync(0xffffffffu, hB, k);
            float b1v = __shfl_sync(0xffffffffu, hB, k + 1);
            ull dA0 = pk2(a0, a0), dA1 = pk2(a1, a1);
            ull dB0 = pk2(b0v, b0v), dB1 = pk2(b1v, b1v);
            fma2(aifA0, dA0, wif[k]);     fma2(agoA0, dA0, wgo[k]);
            fma2(aifB0, dB0, wif[k]);     fma2(agoB0, dB0, wgo[k]);
            fma2(aifA1, dA1, wif[k + 1]); fma2(agoA1, dA1, wgo[k + 1]);
            fma2(aifB1, dB1, wif[k + 1]); fma2(agoB1, dB1, wgo[k + 1]);
        }
        ull aifA = add2(aifA0, aifA1), agoA = add2(agoA0, agoA1);
        ull aifB = add2(aifB0, aifB1), agoB = add2(agoB0, agoB1);

        float aiA, afA, agA, aoA, aiB, afB, agB, aoB;
        upk2(aifA, aiA, afA); upk2(agoA, agA, aoA);
        upk2(aifB, aiB, afB); upk2(agoB, agB, aoB);

        float igA = sigf(aiA), fgA = sigf(afA), ogA = sigf(aoA);
        float igB = sigf(aiB), fgB = sigf(afB), ogB = sigf(aoB);
        cA = fgA * cA + igA * tanhfast(agA);
        cB = fgB * cB + igB * tanhfast(agB);
        hA = ogA * tanhfast(cA);
        hB = ogB * tanhfast(cB);

        hsA[(size_t)t * HH] = hA;
        hsB[(size_t)t * HH] = hB;
    }
}

// ---------------------------------------------------------------------------
// K3: back MLP (R9 version — MEASURED 211µs).
// ---------------------------------------------------------------------------
__global__ __launch_bounds__(256, 2) void k_back(
    const float* __restrict__ W3, const float* __restrict__ b3,
    const float* __restrict__ W4, const float* __restrict__ b4,
    float* __restrict__ out)
{
    __shared__ __align__(16) float hss[64 * 36];   // hs tile [tok][k]
    __shared__ __align__(16) float h3t[64 * 68];   // tanh(hs@W3+b3) TRANSPOSED [k][tok]

    const int tid  = threadIdx.x;
    const int tok0 = blockIdx.x * 64;

    // stage hs tile (64x32)
#pragma unroll
    for (int q = 0; q < 2; q++) {
        int idx = tid + 256 * q;          // 0..511
        int trow = idx >> 3, kq = idx & 7;
        float4 v = *(const float4*)(g_hs + (size_t)(tok0 + trow) * HH + kq * 4);
        *(float4*)(hss + trow * 36 + kq * 4) = v;
    }
    __syncthreads();

    // ---- GEMM W3: [64,32]@[32,64] (scalar) -> h3t TRANSPOSED ----
    {
        const int c2 = tid & 63;
        const int rg = tid >> 6;
        float a2[16];
#pragma unroll
        for (int i = 0; i < 16; i++) a2[i] = 0.f;
#pragma unroll
        for (int k = 0; k < 32; k += 4) {
            float w0 = __ldg(W3 + (k + 0) * 64 + c2);
            float w1 = __ldg(W3 + (k + 1) * 64 + c2);
            float w2 = __ldg(W3 + (k + 2) * 64 + c2);
            float w3 = __ldg(W3 + (k + 3) * 64 + c2);
#pragma unroll
            for (int i = 0; i < 16; i++) {
                float4 xv = *(const float4*)(hss + (rg * 16 + i) * 36 + k);
                a2[i] = fmaf(xv.w, w3, fmaf(xv.z, w2, fmaf(xv.y, w1, fmaf(xv.x, w0, a2[i]))));
            }
        }
        float bb = __ldg(b3 + c2);
#pragma unroll
        for (int i = 0; i < 16; i++)
            h3t[c2 * 68 + rg * 16 + i] = tanh_poly(a2[i] + bb);   // transposed write
    }
    __syncthreads();

    // ---- GEMM W4 (f32x2 token-packed): [64,64]@[64,512], 4 chunks of 128 cols ----
    const int lane = tid & 31;     // cols nc + 4*lane .. +3
    const int wrp  = tid >> 5;     // token octet
#pragma unroll 1
    for (int nc = 0; nc < 512; nc += 128) {
        ull a[4][4];
#pragma unroll
        for (int tp = 0; tp < 4; tp++)
#pragma unroll
            for (int cc = 0; cc < 4; cc++) a[tp][cc] = 0ull;

#pragma unroll 4
        for (int k = 0; k < 64; k++) {
            float4 t01 = *(const float4*)(h3t + k * 68 + wrp * 8);
            float4 t23 = *(const float4*)(h3t + k * 68 + wrp * 8 + 4);
            float4 w   = *(const float4*)(W4 + (size_t)k * 512 + nc + lane * 4);
            ull xv[4] = { pk2(t01.x, t01.y), pk2(t01.z, t01.w),
                          pk2(t23.x, t23.y), pk2(t23.z, t23.w) };
            ull w0 = pk2(w.x, w.x), w1 = pk2(w.y, w.y),
                w2 = pk2(w.z, w.z), w3 = pk2(w.w, w.w);
#pragma unroll
            for (int tp = 0; tp < 4; tp++) {
                fma2(a[tp][0], xv[tp], w0);
                fma2(a[tp][1], xv[tp], w1);
                fma2(a[tp][2], xv[tp], w2);
                fma2(a[tp][3], xv[tp], w3);
            }
        }
        float4 bb = *(const float4*)(b4 + nc + lane * 4);
#pragma unroll
        for (int tp = 0; tp < 4; tp++) {
            float v0l, v0h, v1l, v1h, v2l, v2h, v3l, v3h;
            upk2(a[tp][0], v0l, v0h); upk2(a[tp][1], v1l, v1h);
            upk2(a[tp][2], v2l, v2h); upk2(a[tp][3], v3l, v3h);
            int t0 = tok0 + wrp * 8 + 2 * tp;
            float4 o0 = { v0l + bb.x, v1l + bb.y, v2l + bb.z, v3l + bb.w };
            float4 o1 = { v0h + bb.x, v1h + bb.y, v2h + bb.z, v3h + bb.w };
            *(float4*)(out + (size_t)t0 * 512 + nc + lane * 4)       = o0;
            *(float4*)(out + (size_t)(t0 + 1) * 512 + nc + lane * 4) = o1;
        }
    }
}

// ---------------------------------------------------------------------------
extern "C" void kernel_launch(void* const* d_in, const int* in_sizes, int n_in,
                              void* d_out, int out_size)
{
    const float* x  = (const float*)d_in[0];
    const float* W1 = (const float*)d_in[1];
    const float* b1 = (const float*)d_in[2];
    const float* W2 = (const float*)d_in[3];
    const float* b2 = (const float*)d_in[4];
    const float* Wx = (const float*)d_in[5];
    const float* Wh = (const float*)d_in[6];
    const float* bl = (const float*)d_in[7];
    const float* W3 = (const float*)d_in[8];
    const float* b3 = (const float*)d_in[9];
    const float* W4 = (const float*)d_in[10];
    const float* b4 = (const float*)d_in[11];
    float* out = (float*)d_out;

    k_perm <<<65, 128>>>(Wx, bl);
    k_front<<<NTOK / 64, 256>>>(x, W1, b1, W2, b2);
    k_lstm <<<BB / 2, 32>>>(Wh);
    k_back <<<NTOK / 64, 256>>>(W3, b3, W4, b4, out);
}

// round 12
// speedup vs baseline: 1.3048x; 1.3048x over previous
#include <cuda_runtime.h>
#include <cstdint>

typedef unsigned long long ull;

// Problem constants
#define BB 128
#define SS 1024
#define FF 512
#define HH 32
#define GG 128              // 4*H
#define NTOK (BB*SS)        // 131072

// Scratch (device globals: allocation-free, graph-capturable)
__device__ __align__(16) float g_xg[(size_t)NTOK * GG];  // PERMUTED: [tok][4*j+gate]
__device__ __align__(16) float g_hs[(size_t)NTOK * HH];
__device__ __align__(16) float g_wxp[64 * GG];           // permuted Wx
__device__ __align__(16) float g_blp[GG];                // permuted bl

// ---------------------------------------------------------------------------
// helpers
// ---------------------------------------------------------------------------
__device__ __forceinline__ ull pk2(float lo, float hi) {
    ull r; asm("mov.b64 %0, {%1,%2};" : "=l"(r) : "f"(lo), "f"(hi)); return r;
}
__device__ __forceinline__ void upk2(ull v, float& lo, float& hi) {
    asm("mov.b64 {%0,%1}, %2;" : "=f"(lo), "=f"(hi) : "l"(v));
}
__device__ __forceinline__ void fma2(ull& d, ull a, ull b) {
    asm("fma.rn.f32x2 %0, %1, %2, %0;" : "+l"(d) : "l"(a), "l"(b));
}
__device__ __forceinline__ ull add2(ull a, ull b) {
    ull r; asm("add.rn.f32x2 %0, %1, %2;" : "=l"(r) : "l"(a), "l"(b)); return r;
}

// MUFU-based activations — used ONLY in the LSTM recurrence
__device__ __forceinline__ float sigf(float x) {
    return __fdividef(1.f, 1.f + __expf(-x));
}
__device__ __forceinline__ float tanhfast(float x) {
    return 2.f * __fdividef(1.f, 1.f + __expf(-2.f * x)) - 1.f;
}

// MUFU-free reciprocal: integer seed + 3 Newton steps
__device__ __forceinline__ float rcp_nr(float q) {
    float r = __uint_as_float(0x7EF311C3u - __float_as_uint(q));
    r = r * (2.0f - q * r);
    r = r * (2.0f - q * r);
    r = r * (2.0f - q * r);
    return r;
}
// MUFU-free tanh: rational poly, |err| ~1e-6, pure fma/alu pipe
__device__ __forceinline__ float tanh_poly(float x) {
    const float cl = 7.90531110763549805f;
    x = fminf(cl, fmaxf(-cl, x));
    float x2 = x * x;
    float p = fmaf(x2, -2.76076847742355e-16f, 2.00018790482477e-13f);
    p = fmaf(x2, p, -8.60467152213735e-11f);
    p = fmaf(x2, p,  5.12229709037114e-08f);
    p = fmaf(x2, p,  1.48572235717979e-05f);
    p = fmaf(x2, p,  6.37261928875436e-04f);
    p = fmaf(x2, p,  4.89352455891786e-03f);
    p = p * x;
    float q = fmaf(x2, 1.19825839466702e-06f, 1.18534705686654e-04f);
    q = fmaf(x2, q, 2.26843463243900e-03f);
    q = fmaf(x2, q, 4.89352518554385e-03f);
    return p * rcp_nr(q);
}

// ---------------------------------------------------------------------------
// K0: permute Wx[64,128] and bl[128]: wxp[k][4j+g] = Wx[k][32g+j]
// ---------------------------------------------------------------------------
__global__ void k_perm(const float* __restrict__ Wx, const float* __restrict__ bl)
{
    int t = threadIdx.x;          // 0..127  (= 4j+g)
    int j = t >> 2, g = t & 3;
    int kb = blockIdx.x;
    if (kb < 64) g_wxp[kb * GG + t] = Wx[kb * GG + 32 * g + j];
    else         g_blp[t] = bl[32 * g + j];
}

// ---------------------------------------------------------------------------
// K1: front MLP (R8/R10 version — measured good).
// ---------------------------------------------------------------------------
__global__ __launch_bounds__(256) void k_front(
    const float* __restrict__ x,  const float* __restrict__ W1, const float* __restrict__ b1,
    const float* __restrict__ W2, const float* __restrict__ b2)
{
    __shared__ float xs [64 * 68];
    __shared__ float h1s[64 * 36];
    __shared__ float h2s[64 * 68];

    const int tid  = threadIdx.x;
    const int tok0 = blockIdx.x * 64;

    // ---- GEMM1: [64,512] @ [512,32] ----
    const int c  = tid & 31;
    const int r8 = tid >> 5;
    float acc[8];
#pragma unroll
    for (int i = 0; i < 8; i++) acc[i] = 0.f;

    for (int kk = 0; kk < FF; kk += 64) {
        __syncthreads();
#pragma unroll
        for (int q = 0; q < 4; q++) {
            int idx  = tid + 256 * q;
            int trow = idx >> 4;
            int kq   = idx & 15;
            float4 v = *(const float4*)(x + (size_t)(tok0 + trow) * FF + kk + kq * 4);
            *(float4*)(xs + trow * 68 + kq * 4) = v;
        }
        __syncthreads();
#pragma unroll 4
        for (int k = 0; k < 64; k += 4) {
            float w0 = __ldg(W1 + (kk + k + 0) * 32 + c);
            float w1 = __ldg(W1 + (kk + k + 1) * 32 + c);
            float w2 = __ldg(W1 + (kk + k + 2) * 32 + c);
            float w3 = __ldg(W1 + (kk + k + 3) * 32 + c);
#pragma unroll
            for (int i = 0; i < 8; i++) {
                float4 xv = *(const float4*)(xs + (r8 * 8 + i) * 68 + k);
                acc[i] = fmaf(xv.w, w3, fmaf(xv.z, w2, fmaf(xv.y, w1, fmaf(xv.x, w0, acc[i]))));
            }
        }
    }
    {
        float bb = __ldg(b1 + c);
#pragma unroll
        for (int i = 0; i < 8; i++)
            h1s[(r8 * 8 + i) * 36 + c] = tanh_poly(acc[i] + bb);
    }
    __syncthreads();

    // ---- GEMM2: [64,32] @ [32,64] ----
    {
        const int c2 = tid & 63;
        const int rg = tid >> 6;
        float a2[16];
#pragma unroll
        for (int i = 0; i < 16; i++) a2[i] = 0.f;
#pragma unroll
        for (int k = 0; k < 32; k += 4) {
            float w0 = __ldg(W2 + (k + 0) * 64 + c2);
            float w1 = __ldg(W2 + (k + 1) * 64 + c2);
            float w2 = __ldg(W2 + (k + 2) * 64 + c2);
            float w3 = __ldg(W2 + (k + 3) * 64 + c2);
#pragma unroll
            for (int i = 0; i < 16; i++) {
                float4 xv = *(const float4*)(h1s + (rg * 16 + i) * 36 + k);
                a2[i] = fmaf(xv.w, w3, fmaf(xv.z, w2, fmaf(xv.y, w1, fmaf(xv.x, w0, a2[i]))));
            }
        }
        float bb = __ldg(b2 + c2);
#pragma unroll
        for (int i = 0; i < 16; i++)
            h2s[(rg * 16 + i) * 68 + c2] = tanh_poly(a2[i] + bb);
    }
    __syncthreads();

    // ---- GEMM3: [64,64] @ wxp[64,128] + blp -> g_xg (permuted layout) ----
    {
        const int c3 = tid & 127;
        const int rg = tid >> 7;
        float a3[32];
#pragma unroll
        for (int i = 0; i < 32; i++) a3[i] = 0.f;
#pragma unroll 4
        for (int k = 0; k < 64; k += 4) {
            float w0 = g_wxp[(k + 0) * GG + c3];
            float w1 = g_wxp[(k + 1) * GG + c3];
            float w2 = g_wxp[(k + 2) * GG + c3];
            float w3 = g_wxp[(k + 3) * GG + c3];
#pragma unroll
            for (int i = 0; i < 32; i++) {
                float4 xv = *(const float4*)(h2s + (rg * 32 + i) * 68 + k);
                a3[i] = fmaf(xv.w, w3, fmaf(xv.z, w2, fmaf(xv.y, w1, fmaf(xv.x, w0, a3[i]))));
            }
        }
        float bb = g_blp[c3];
#pragma unroll
        for (int i = 0; i < 32; i++)
            g_xg[(size_t)(tok0 + rg * 32 + i) * GG + c3] = a3[i] + bb;
    }
}

// ---------------------------------------------------------------------------
// K2: LSTM scan — SINGLE chain per warp (grid=128, block=32), but h broadcast
// via SMEM dup-pairs (1 STS.64 + syncwarp + 16 LDS.64) instead of 32 SHFL.
// Theory: shfl issue throughput is the binding resource at ~460cyc/step.
// Prefetch ring depth 4. Double-buffered h array.
// ---------------------------------------------------------------------------
__global__ __launch_bounds__(32, 1) void k_lstm(const float* __restrict__ Wh)
{
    __shared__ __align__(16) float hd[2][64];    // dup pairs: hd[buf][2k]=hd[buf][2k+1]=h_k

    const int b = blockIdx.x;
    const int j = threadIdx.x;

    ull wif[HH], wgo[HH];
#pragma unroll
    for (int k = 0; k < HH; k++) {
        const float* row = Wh + k * GG;
        wif[k] = pk2(__ldg(row + j),      __ldg(row + 32 + j));
        wgo[k] = pk2(__ldg(row + 64 + j), __ldg(row + 96 + j));
    }

    const float4* xgb = reinterpret_cast<const float4*>(g_xg) + (size_t)b * SS * 32 + j;
    float* hsb = g_hs + (size_t)b * SS * HH + j;

    float c = 0.f, h = 0.f;
    float4 pf[4];
#pragma unroll
    for (int q = 0; q < 4; q++) pf[q] = __ldg(xgb + (size_t)q * 32);

#pragma unroll 2
    for (int t = 0; t < SS; t++) {
        float4 g4 = pf[t & 3];
        int tn = (t + 4 < SS) ? (t + 4) : (SS - 1);
        pf[t & 3] = __ldg(xgb + (size_t)tn * 32);

        // publish h as a dup pair (STS.64), then sync the warp
        float* hb = hd[t & 1];
        *(float2*)(hb + 2 * j) = make_float2(h, h);
        __syncwarp();

        ull aif0 = pk2(g4.x, g4.y), ago0 = pk2(g4.z, g4.w);
        ull aif1 = 0ull, ago1 = 0ull;

#pragma unroll
        for (int k = 0; k < HH; k += 2) {
            ull d0 = *(const ull*)(hb + 2 * k);        // LDS.64 dup pair (broadcast)
            ull d1 = *(const ull*)(hb + 2 * k + 2);
            fma2(aif0, d0, wif[k]);     fma2(ago0, d0, wgo[k]);
            fma2(aif1, d1, wif[k + 1]); fma2(ago1, d1, wgo[k + 1]);
        }
        ull aif = add2(aif0, aif1), ago = add2(ago0, ago1);
        float ai, af, ag, ao;
        upk2(aif, ai, af); upk2(ago, ag, ao);

        float ig = sigf(ai), fg = sigf(af), og = sigf(ao);
        c = fg * c + ig * tanhfast(ag);
        h = og * tanhfast(c);

        hsb[(size_t)t * HH] = h;
    }
}

// ---------------------------------------------------------------------------
// K3: back MLP (R9/R10 version — MEASURED 211µs).
// ---------------------------------------------------------------------------
__global__ __launch_bounds__(256, 2) void k_back(
    const float* __restrict__ W3, const float* __restrict__ b3,
    const float* __restrict__ W4, const float* __restrict__ b4,
    float* __restrict__ out)
{
    __shared__ __align__(16) float hss[64 * 36];   // hs tile [tok][k]
    __shared__ __align__(16) float h3t[64 * 68];   // tanh(hs@W3+b3) TRANSPOSED [k][tok]

    const int tid  = threadIdx.x;
    const int tok0 = blockIdx.x * 64;

    // stage hs tile (64x32)
#pragma unroll
    for (int q = 0; q < 2; q++) {
        int idx = tid + 256 * q;          // 0..511
        int trow = idx >> 3, kq = idx & 7;
        float4 v = *(const float4*)(g_hs + (size_t)(tok0 + trow) * HH + kq * 4);
        *(float4*)(hss + trow * 36 + kq * 4) = v;
    }
    __syncthreads();

    // ---- GEMM W3: [64,32]@[32,64] (scalar) -> h3t TRANSPOSED ----
    {
        const int c2 = tid & 63;
        const int rg = tid >> 6;
        float a2[16];
#pragma unroll
        for (int i = 0; i < 16; i++) a2[i] = 0.f;
#pragma unroll
        for (int k = 0; k < 32; k += 4) {
            float w0 = __ldg(W3 + (k + 0) * 64 + c2);
            float w1 = __ldg(W3 + (k + 1) * 64 + c2);
            float w2 = __ldg(W3 + (k + 2) * 64 + c2);
            float w3 = __ldg(W3 + (k + 3) * 64 + c2);
#pragma unroll
            for (int i = 0; i < 16; i++) {
                float4 xv = *(const float4*)(hss + (rg * 16 + i) * 36 + k);
                a2[i] = fmaf(xv.w, w3, fmaf(xv.z, w2, fmaf(xv.y, w1, fmaf(xv.x, w0, a2[i]))));
            }
        }
        float bb = __ldg(b3 + c2);
#pragma unroll
        for (int i = 0; i < 16; i++)
            h3t[c2 * 68 + rg * 16 + i] = tanh_poly(a2[i] + bb);   // transposed write
    }
    __syncthreads();

    // ---- GEMM W4 (f32x2 token-packed): [64,64]@[64,512], 4 chunks of 128 cols ----
    const int lane = tid & 31;     // cols nc + 4*lane .. +3
    const int wrp  = tid >> 5;     // token octet
#pragma unroll 1
    for (int nc = 0; nc < 512; nc += 128) {
        ull a[4][4];
#pragma unroll
        for (int tp = 0; tp < 4; tp++)
#pragma unroll
            for (int cc = 0; cc < 4; cc++) a[tp][cc] = 0ull;

#pragma unroll 4
        for (int k = 0; k < 64; k++) {
            float4 t01 = *(const float4*)(h3t + k * 68 + wrp * 8);
            float4 t23 = *(const float4*)(h3t + k * 68 + wrp * 8 + 4);
            float4 w   = *(const float4*)(W4 + (size_t)k * 512 + nc + lane * 4);
            ull xv[4] = { pk2(t01.x, t01.y), pk2(t01.z, t01.w),
                          pk2(t23.x, t23.y), pk2(t23.z, t23.w) };
            ull w0 = pk2(w.x, w.x), w1 = pk2(w.y, w.y),
                w2 = pk2(w.z, w.z), w3 = pk2(w.w, w.w);
#pragma unroll
            for (int tp = 0; tp < 4; tp++) {
                fma2(a[tp][0], xv[tp], w0);
                fma2(a[tp][1], xv[tp], w1);
                fma2(a[tp][2], xv[tp], w2);
                fma2(a[tp][3], xv[tp], w3);
            }
        }
        float4 bb = *(const float4*)(b4 + nc + lane * 4);
#pragma unroll
        for (int tp = 0; tp < 4; tp++) {
            float v0l, v0h, v1l, v1h, v2l, v2h, v3l, v3h;
            upk2(a[tp][0], v0l, v0h); upk2(a[tp][1], v1l, v1h);
            upk2(a[tp][2], v2l, v2h); upk2(a[tp][3], v3l, v3h);
            int t0 = tok0 + wrp * 8 + 2 * tp;
            float4 o0 = { v0l + bb.x, v1l + bb.y, v2l + bb.z, v3l + bb.w };
            float4 o1 = { v0h + bb.x, v1h + bb.y, v2h + bb.z, v3h + bb.w };
            *(float4*)(out + (size_t)t0 * 512 + nc + lane * 4)       = o0;
            *(float4*)(out + (size_t)(t0 + 1) * 512 + nc + lane * 4) = o1;
        }
    }
}

// ---------------------------------------------------------------------------
extern "C" void kernel_launch(void* const* d_in, const int* in_sizes, int n_in,
                              void* d_out, int out_size)
{
    const float* x  = (const float*)d_in[0];
    const float* W1 = (const float*)d_in[1];
    const float* b1 = (const float*)d_in[2];
    const float* W2 = (const float*)d_in[3];
    const float* b2 = (const float*)d_in[4];
    const float* Wx = (const float*)d_in[5];
    const float* Wh = (const float*)d_in[6];
    const float* bl = (const float*)d_in[7];
    const float* W3 = (const float*)d_in[8];
    const float* b3 = (const float*)d_in[9];
    const float* W4 = (const float*)d_in[10];
    const float* b4 = (const float*)d_in[11];
    float* out = (float*)d_out;

    k_perm <<<65, 128>>>(Wx, bl);
    k_front<<<NTOK / 64, 256>>>(x, W1, b1, W2, b2);
    k_lstm <<<BB, 32>>>(Wh);
    k_back <<<NTOK / 64, 256>>>(W3, b3, W4, b4, out);
}

// round 13
// speedup vs baseline: 1.6546x; 1.2681x over previous
#include <cuda_runtime.h>
#include <cstdint>

typedef unsigned long long ull;

// Problem constants
#define BB 128
#define SS 1024
#define FF 512
#define HH 32
#define GG 128              // 4*H
#define NTOK (BB*SS)        // 131072

// Scratch (device globals: allocation-free, graph-capturable)
__device__ __align__(16) float g_xg[(size_t)NTOK * GG];  // PERMUTED: [tok][4*j+gate]
__device__ __align__(16) float g_hs[(size_t)NTOK * HH];
__device__ __align__(16) float g_wxp[64 * GG];           // permuted Wx
__device__ __align__(16) float g_blp[GG];                // permuted bl

// ---------------------------------------------------------------------------
// helpers
// ---------------------------------------------------------------------------
__device__ __forceinline__ ull pk2(float lo, float hi) {
    ull r; asm("mov.b64 %0, {%1,%2};" : "=l"(r) : "f"(lo), "f"(hi)); return r;
}
__device__ __forceinline__ void upk2(ull v, float& lo, float& hi) {
    asm("mov.b64 {%0,%1}, %2;" : "=f"(lo), "=f"(hi) : "l"(v));
}
__device__ __forceinline__ void fma2(ull& d, ull a, ull b) {
    asm("fma.rn.f32x2 %0, %1, %2, %0;" : "+l"(d) : "l"(a), "l"(b));
}
__device__ __forceinline__ ull add2(ull a, ull b) {
    ull r; asm("add.rn.f32x2 %0, %1, %2;" : "=l"(r) : "l"(a), "l"(b)); return r;
}

// MUFU-based activations — used ONLY in the LSTM recurrence
__device__ __forceinline__ float sigf(float x) {
    return __fdividef(1.f, 1.f + __expf(-x));
}
__device__ __forceinline__ float tanhfast(float x) {
    return 2.f * __fdividef(1.f, 1.f + __expf(-2.f * x)) - 1.f;
}

// MUFU-free reciprocal: integer seed + 3 Newton steps
__device__ __forceinline__ float rcp_nr(float q) {
    float r = __uint_as_float(0x7EF311C3u - __float_as_uint(q));
    r = r * (2.0f - q * r);
    r = r * (2.0f - q * r);
    r = r * (2.0f - q * r);
    return r;
}
// MUFU-free tanh: rational poly, |err| ~1e-6, pure fma/alu pipe
__device__ __forceinline__ float tanh_poly(float x) {
    const float cl = 7.90531110763549805f;
    x = fminf(cl, fmaxf(-cl, x));
    float x2 = x * x;
    float p = fmaf(x2, -2.76076847742355e-16f, 2.00018790482477e-13f);
    p = fmaf(x2, p, -8.60467152213735e-11f);
    p = fmaf(x2, p,  5.12229709037114e-08f);
    p = fmaf(x2, p,  1.48572235717979e-05f);
    p = fmaf(x2, p,  6.37261928875436e-04f);
    p = fmaf(x2, p,  4.89352455891786e-03f);
    p = p * x;
    float q = fmaf(x2, 1.19825839466702e-06f, 1.18534705686654e-04f);
    q = fmaf(x2, q, 2.26843463243900e-03f);
    q = fmaf(x2, q, 4.89352518554385e-03f);
    return p * rcp_nr(q);
}

// ---------------------------------------------------------------------------
// K0: permute Wx[64,128] and bl[128]: wxp[k][4j+g] = Wx[k][32g+j]
// ---------------------------------------------------------------------------
__global__ void k_perm(const float* __restrict__ Wx, const float* __restrict__ bl)
{
    int t = threadIdx.x;          // 0..127  (= 4j+g)
    int j = t >> 2, g = t & 3;
    int kb = blockIdx.x;
    if (kb < 64) g_wxp[kb * GG + t] = Wx[kb * GG + 32 * g + j];
    else         g_blp[t] = bl[32 * g + j];
}

// ---------------------------------------------------------------------------
// K1: front MLP (R9 version — inferred −25µs vs R8).
// GEMM1/GEMM2 scalar; GEMM2 writes h2 TRANSPOSED [k][tok];
// GEMM3 token-packed f32x2 -> g_xg (permuted).
// CTA: 256 threads, 64 tokens. grid = 2048.
// ---------------------------------------------------------------------------
__global__ __launch_bounds__(256, 2) void k_front(
    const float* __restrict__ x,  const float* __restrict__ W1, const float* __restrict__ b1,
    const float* __restrict__ W2, const float* __restrict__ b2)
{
    __shared__ __align__(16) float xs [64 * 68];   // x tile, K-chunk of 64
    __shared__ __align__(16) float h1s[64 * 36];   // tanh(x@W1+b1) [tok][k]
    __shared__ __align__(16) float h2t[64 * 68];   // tanh(h1@W2+b2) TRANSPOSED [k][tok]

    const int tid  = threadIdx.x;
    const int tok0 = blockIdx.x * 64;

    // ---- GEMM1: [64,512] @ [512,32] (scalar) ----
    const int c  = tid & 31;
    const int r8 = tid >> 5;
    float acc[8];
#pragma unroll
    for (int i = 0; i < 8; i++) acc[i] = 0.f;

    for (int kk = 0; kk < FF; kk += 64) {
        __syncthreads();
#pragma unroll
        for (int q = 0; q < 4; q++) {
            int idx  = tid + 256 * q;
            int trow = idx >> 4;
            int kq   = idx & 15;
            float4 v = *(const float4*)(x + (size_t)(tok0 + trow) * FF + kk + kq * 4);
            *(float4*)(xs + trow * 68 + kq * 4) = v;
        }
        __syncthreads();
#pragma unroll 4
        for (int k = 0; k < 64; k += 4) {
            float w0 = __ldg(W1 + (kk + k + 0) * 32 + c);
            float w1 = __ldg(W1 + (kk + k + 1) * 32 + c);
            float w2 = __ldg(W1 + (kk + k + 2) * 32 + c);
            float w3 = __ldg(W1 + (kk + k + 3) * 32 + c);
#pragma unroll
            for (int i = 0; i < 8; i++) {
                float4 xv = *(const float4*)(xs + (r8 * 8 + i) * 68 + k);
                acc[i] = fmaf(xv.w, w3, fmaf(xv.z, w2, fmaf(xv.y, w1, fmaf(xv.x, w0, acc[i]))));
            }
        }
    }
    {
        float bb = __ldg(b1 + c);
#pragma unroll
        for (int i = 0; i < 8; i++)
            h1s[(r8 * 8 + i) * 36 + c] = tanh_poly(acc[i] + bb);
    }
    __syncthreads();

    // ---- GEMM2: [64,32] @ [32,64] (scalar) -> h2t TRANSPOSED ----
    {
        const int c2 = tid & 63;
        const int rg = tid >> 6;
        float a2[16];
#pragma unroll
        for (int i = 0; i < 16; i++) a2[i] = 0.f;
#pragma unroll
        for (int k = 0; k < 32; k += 4) {
            float w0 = __ldg(W2 + (k + 0) * 64 + c2);
            float w1 = __ldg(W2 + (k + 1) * 64 + c2);
            float w2 = __ldg(W2 + (k + 2) * 64 + c2);
            float w3 = __ldg(W2 + (k + 3) * 64 + c2);
#pragma unroll
            for (int i = 0; i < 16; i++) {
                float4 xv = *(const float4*)(h1s + (rg * 16 + i) * 36 + k);
                a2[i] = fmaf(xv.w, w3, fmaf(xv.z, w2, fmaf(xv.y, w1, fmaf(xv.x, w0, a2[i]))));
            }
        }
        float bb = __ldg(b2 + c2);
#pragma unroll
        for (int i = 0; i < 16; i++)
            h2t[c2 * 68 + rg * 16 + i] = tanh_poly(a2[i] + bb);   // transposed write
    }
    __syncthreads();

    // ---- GEMM3 (f32x2 token-packed): [64,64] @ wxp[64,128] + blp -> g_xg ----
    {
        const int lane = tid & 31;      // cols 4*lane .. 4*lane+3 (permuted col space)
        const int wrp  = tid >> 5;      // token octet: tokens wrp*8 .. wrp*8+7
        ull a[4][4];                    // [tokpair][col]
#pragma unroll
        for (int tp = 0; tp < 4; tp++)
#pragma unroll
            for (int cc = 0; cc < 4; cc++) a[tp][cc] = 0ull;

#pragma unroll 4
        for (int k = 0; k < 64; k++) {
            float4 t01 = *(const float4*)(h2t + k * 68 + wrp * 8);
            float4 t23 = *(const float4*)(h2t + k * 68 + wrp * 8 + 4);
            float4 w   = *(const float4*)(g_wxp + (size_t)k * GG + lane * 4);
            ull xv[4] = { pk2(t01.x, t01.y), pk2(t01.z, t01.w),
                          pk2(t23.x, t23.y), pk2(t23.z, t23.w) };
            ull w0 = pk2(w.x, w.x), w1 = pk2(w.y, w.y),
                w2 = pk2(w.z, w.z), w3 = pk2(w.w, w.w);
#pragma unroll
            for (int tp = 0; tp < 4; tp++) {
                fma2(a[tp][0], xv[tp], w0);
                fma2(a[tp][1], xv[tp], w1);
                fma2(a[tp][2], xv[tp], w2);
                fma2(a[tp][3], xv[tp], w3);
            }
        }
        float4 bb = *(const float4*)(g_blp + lane * 4);
#pragma unroll
        for (int tp = 0; tp < 4; tp++) {
            float v0l, v0h, v1l, v1h, v2l, v2h, v3l, v3h;
            upk2(a[tp][0], v0l, v0h); upk2(a[tp][1], v1l, v1h);
            upk2(a[tp][2], v2l, v2h); upk2(a[tp][3], v3l, v3h);
            int t0 = tok0 + wrp * 8 + 2 * tp;
            float4 o0 = { v0l + bb.x, v1l + bb.y, v2l + bb.z, v3l + bb.w };
            float4 o1 = { v0h + bb.x, v1h + bb.y, v2h + bb.z, v3h + bb.w };
            *(float4*)(g_xg + (size_t)t0 * GG + lane * 4)       = o0;
            *(float4*)(g_xg + (size_t)(t0 + 1) * GG + lane * 4) = o1;
        }
    }
}

// ---------------------------------------------------------------------------
// K2: LSTM scan (R8 shfl version — confirmed best).
// One warp per batch (grid=128, block=32). Thread j = unit j.
// Permuted xg: one LDG.128 per step. Prefetch ring depth 4.
// ---------------------------------------------------------------------------
__global__ __launch_bounds__(32, 1) void k_lstm(const float* __restrict__ Wh)
{
    const int b = blockIdx.x;
    const int j = threadIdx.x;

    ull wif[HH], wgo[HH];
#pragma unroll
    for (int k = 0; k < HH; k++) {
        const float* row = Wh + k * GG;
        wif[k] = pk2(__ldg(row + j),      __ldg(row + 32 + j));
        wgo[k] = pk2(__ldg(row + 64 + j), __ldg(row + 96 + j));
    }

    const float4* xgb = reinterpret_cast<const float4*>(g_xg) + (size_t)b * SS * 32 + j;
    float* hsb = g_hs + (size_t)b * SS * HH + j;

    float c = 0.f, h = 0.f;
    float4 pf[4];
#pragma unroll
    for (int q = 0; q < 4; q++) pf[q] = __ldg(xgb + (size_t)q * 32);

#pragma unroll 4
    for (int t = 0; t < SS; t++) {
        float4 g4 = pf[t & 3];
        int tn = (t + 4 < SS) ? (t + 4) : (SS - 1);
        pf[t & 3] = __ldg(xgb + (size_t)tn * 32);

        ull aif0 = pk2(g4.x, g4.y), ago0 = pk2(g4.z, g4.w);
        ull aif1 = 0ull, ago1 = 0ull;

#pragma unroll
        for (int k = 0; k < HH; k += 2) {
            float h0 = __shfl_sync(0xffffffffu, h, k);
            float h1 = __shfl_sync(0xffffffffu, h, k + 1);
            ull d0 = pk2(h0, h0), d1 = pk2(h1, h1);
            fma2(aif0, d0, wif[k]);     fma2(ago0, d0, wgo[k]);
            fma2(aif1, d1, wif[k + 1]); fma2(ago1, d1, wgo[k + 1]);
        }
        ull aif = add2(aif0, aif1), ago = add2(ago0, ago1);
        float ai, af, ag, ao;
        upk2(aif, ai, af); upk2(ago, ag, ao);

        float ig = sigf(ai), fg = sigf(af), og = sigf(ao);
        c = fg * c + ig * tanhfast(ag);
        h = og * tanhfast(c);

        hsb[(size_t)t * HH] = h;
    }
}

// ---------------------------------------------------------------------------
// K3: back MLP (R9 version — MEASURED ~211µs).
// ---------------------------------------------------------------------------
__global__ __launch_bounds__(256, 2) void k_back(
    const float* __restrict__ W3, const float* __restrict__ b3,
    const float* __restrict__ W4, const float* __restrict__ b4,
    float* __restrict__ out)
{
    __shared__ __align__(16) float hss[64 * 36];   // hs tile [tok][k]
    __shared__ __align__(16) float h3t[64 * 68];   // tanh(hs@W3+b3) TRANSPOSED [k][tok]

    const int tid  = threadIdx.x;
    const int tok0 = blockIdx.x * 64;

    // stage hs tile (64x32)
#pragma unroll
    for (int q = 0; q < 2; q++) {
        int idx = tid + 256 * q;          // 0..511
        int trow = idx >> 3, kq = idx & 7;
        float4 v = *(const float4*)(g_hs + (size_t)(tok0 + trow) * HH + kq * 4);
        *(float4*)(hss + trow * 36 + kq * 4) = v;
    }
    __syncthreads();

    // ---- GEMM W3: [64,32]@[32,64] (scalar) -> h3t TRANSPOSED ----
    {
        const int c2 = tid & 63;
        const int rg = tid >> 6;
        float a2[16];
#pragma unroll
        for (int i = 0; i < 16; i++) a2[i] = 0.f;
#pragma unroll
        for (int k = 0; k < 32; k += 4) {
            float w0 = __ldg(W3 + (k + 0) * 64 + c2);
            float w1 = __ldg(W3 + (k + 1) * 64 + c2);
            float w2 = __ldg(W3 + (k + 2) * 64 + c2);
            float w3 = __ldg(W3 + (k + 3) * 64 + c2);
#pragma unroll
            for (int i = 0; i < 16; i++) {
                float4 xv = *(const float4*)(hss + (rg * 16 + i) * 36 + k);
                a2[i] = fmaf(xv.w, w3, fmaf(xv.z, w2, fmaf(xv.y, w1, fmaf(xv.x, w0, a2[i]))));
            }
        }
        float bb = __ldg(b3 + c2);
#pragma unroll
        for (int i = 0; i < 16; i++)
            h3t[c2 * 68 + rg * 16 + i] = tanh_poly(a2[i] + bb);   // transposed write
    }
    __syncthreads();

    // ---- GEMM W4 (f32x2 token-packed): [64,64]@[64,512], 4 chunks of 128 cols ----
    const int lane = tid & 31;     // cols nc + 4*lane .. +3
    const int wrp  = tid >> 5;     // token octet
#pragma unroll 1
    for (int nc = 0; nc < 512; nc += 128) {
        ull a[4][4];
#pragma unroll
        for (int tp = 0; tp < 4; tp++)
#pragma unroll
            for (int cc = 0; cc < 4; cc++) a[tp][cc] = 0ull;

#pragma unroll 4
        for (int k = 0; k < 64; k++) {
            float4 t01 = *(const float4*)(h3t + k * 68 + wrp * 8);
            float4 t23 = *(const float4*)(h3t + k * 68 + wrp * 8 + 4);
            float4 w   = *(const float4*)(W4 + (size_t)k * 512 + nc + lane * 4);
            ull xv[4] = { pk2(t01.x, t01.y), pk2(t01.z, t01.w),
                          pk2(t23.x, t23.y), pk2(t23.z, t23.w) };
            ull w0 = pk2(w.x, w.x), w1 = pk2(w.y, w.y),
                w2 = pk2(w.z, w.z), w3 = pk2(w.w, w.w);
#pragma unroll
            for (int tp = 0; tp < 4; tp++) {
                fma2(a[tp][0], xv[tp], w0);
                fma2(a[tp][1], xv[tp], w1);
                fma2(a[tp][2], xv[tp], w2);
                fma2(a[tp][3], xv[tp], w3);
            }
        }
        float4 bb = *(const float4*)(b4 + nc + lane * 4);
#pragma unroll
        for (int tp = 0; tp < 4; tp++) {
            float v0l, v0h, v1l, v1h, v2l, v2h, v3l, v3h;
            upk2(a[tp][0], v0l, v0h); upk2(a[tp][1], v1l, v1h);
            upk2(a[tp][2], v2l, v2h); upk2(a[tp][3], v3l, v3h);
            int t0 = tok0 + wrp * 8 + 2 * tp;
            float4 o0 = { v0l + bb.x, v1l + bb.y, v2l + bb.z, v3l + bb.w };
            float4 o1 = { v0h + bb.x, v1h + bb.y, v2h + bb.z, v3h + bb.w };
            *(float4*)(out + (size_t)t0 * 512 + nc + lane * 4)       = o0;
            *(float4*)(out + (size_t)(t0 + 1) * 512 + nc + lane * 4) = o1;
        }
    }
}

// ---------------------------------------------------------------------------
extern "C" void kernel_launch(void* const* d_in, const int* in_sizes, int n_in,
                              void* d_out, int out_size)
{
    const float* x  = (const float*)d_in[0];
    const float* W1 = (const float*)d_in[1];
    const float* b1 = (const float*)d_in[2];
    const float* W2 = (const float*)d_in[3];
    const float* b2 = (const float*)d_in[4];
    const float* Wx = (const float*)d_in[5];
    const float* Wh = (const float*)d_in[6];
    const float* bl = (const float*)d_in[7];
    const float* W3 = (const float*)d_in[8];
    const float* b3 = (const float*)d_in[9];
    const float* W4 = (const float*)d_in[10];
    const float* b4 = (const float*)d_in[11];
    float* out = (float*)d_out;

    k_perm <<<65, 128>>>(Wx, bl);
    k_front<<<NTOK / 64, 256>>>(x, W1, b1, W2, b2);
    k_lstm <<<BB, 32>>>(Wh);
    k_back <<<NTOK / 64, 256>>>(W3, b3, W4, b4, out);
}